// round 17
// baseline (speedup 1.0000x reference)
#include <cuda_runtime.h>
#include <cuda_fp16.h>
#include <cstdint>

// ============================================================================
// Problem constants
// ============================================================================
#define M_TOK   8192        // B*S tokens
#define K_DIM   4096        // IN
#define N_DIM   4096        // OUT

#define BM 128
#define BN 128
#define BK 64
#define NK (K_DIM / BK)     // 64 k-tiles
#define STAGES 3
#define THREADS 256         // 8 warps: 4 (M) x 2 (N), warp tile 32x64

#define TILE_ROW_BYTES 128                       // 64 fp16
#define A_TILE_BYTES (BM * TILE_ROW_BYTES)       // 16384
#define B_TILE_BYTES (BN * TILE_ROW_BYTES)       // 16384
#define STAGE_BYTES  (A_TILE_BYTES + B_TILE_BYTES)   // 32768
#define SMEM_TOTAL   (STAGES * STAGE_BYTES)          // 98304 (2 CTAs/SM)

// ============================================================================
// Device scratch (no dynamic allocation allowed)
// ============================================================================
__device__ __align__(1024) __half g_xq[(size_t)M_TOK * K_DIM];   // 64 MB
__device__ __align__(1024) __half g_wb[(size_t)N_DIM * K_DIM];   // 32 MB
__device__ float g_alpha[M_TOK];

// ============================================================================
// PTX helpers
// ============================================================================
__device__ __forceinline__ uint32_t smem_to_u32(const void* p) {
    uint32_t a;
    asm("{ .reg .u64 t; cvta.to.shared.u64 t, %1; cvt.u32.u64 %0, t; }"
        : "=r"(a) : "l"(p));
    return a;
}

__device__ __forceinline__ void cp_async16(uint32_t smem_addr, const void* gptr) {
    asm volatile("cp.async.cg.shared.global [%0], [%1], 16;"
                 :: "r"(smem_addr), "l"(gptr) : "memory");
}
__device__ __forceinline__ void cp_commit() {
    asm volatile("cp.async.commit_group;" ::: "memory");
}
template <int N>
__device__ __forceinline__ void cp_wait() {
    asm volatile("cp.async.wait_group %0;" :: "n"(N) : "memory");
}

__device__ __forceinline__ void ldsm_x4(uint32_t addr, uint32_t* r) {
    asm volatile("ldmatrix.sync.aligned.m8n8.x4.shared.b16 {%0,%1,%2,%3}, [%4];"
                 : "=r"(r[0]), "=r"(r[1]), "=r"(r[2]), "=r"(r[3]) : "r"(addr));
}

// m16n8k16 fp16 inputs, fp32 accumulate
__device__ __forceinline__ void mma_f16(float* c, uint32_t a0, uint32_t a1,
                                        uint32_t a2, uint32_t a3,
                                        uint32_t b0, uint32_t b1) {
    asm volatile(
        "mma.sync.aligned.m16n8k16.row.col.f32.f16.f16.f32 "
        "{%0,%1,%2,%3}, {%4,%5,%6,%7}, {%8,%9}, {%0,%1,%2,%3};"
        : "+f"(c[0]), "+f"(c[1]), "+f"(c[2]), "+f"(c[3])
        : "r"(a0), "r"(a1), "r"(a2), "r"(a3), "r"(b0), "r"(b1));
}

// ============================================================================
// Kernel 1: per-token absmax quantize x -> fp16 (exact small ints),
// alpha = gamma/127*scale
// ============================================================================
__global__ void __launch_bounds__(128)
quant_kernel(const float* __restrict__ x, const float* __restrict__ scale_p,
             __half* __restrict__ xq, float* __restrict__ alpha)
{
    const int token = blockIdx.x;
    const int tid = threadIdx.x;
    const float4* xr = reinterpret_cast<const float4*>(x + (size_t)token * K_DIM);

    float4 v[8];
    float m = 0.0f;
#pragma unroll
    for (int i = 0; i < 8; i++) {
        v[i] = xr[tid + i * 128];
        m = fmaxf(m, fmaxf(fmaxf(fabsf(v[i].x), fabsf(v[i].y)),
                           fmaxf(fabsf(v[i].z), fabsf(v[i].w))));
    }
#pragma unroll
    for (int o = 16; o; o >>= 1) m = fmaxf(m, __shfl_xor_sync(0xFFFFFFFFu, m, o));

    __shared__ float wmax[4];
    __shared__ float s_inv;
    if ((tid & 31) == 0) wmax[tid >> 5] = m;
    __syncthreads();
    if (tid == 0) {
        float g = fmaxf(fmaxf(wmax[0], wmax[1]), fmaxf(wmax[2], wmax[3]));
        g = fmaxf(g, 1e-5f);
        s_inv = 127.0f / g;
        alpha[token] = g * (1.0f / 127.0f) * scale_p[0];
    }
    __syncthreads();
    const float inv = s_inv;

    __half2* xqr = reinterpret_cast<__half2*>(xq + (size_t)token * K_DIM);
#pragma unroll
    for (int i = 0; i < 8; i++) {
        float q0 = fminf(fmaxf(rintf(v[i].x * inv), -127.0f), 127.0f);
        float q1 = fminf(fmaxf(rintf(v[i].y * inv), -127.0f), 127.0f);
        float q2 = fminf(fmaxf(rintf(v[i].z * inv), -127.0f), 127.0f);
        float q3 = fminf(fmaxf(rintf(v[i].w * inv), -127.0f), 127.0f);
        __half2 p0, p1;
        p0.x = __float2half_rn(q0); p0.y = __float2half_rn(q1);
        p1.x = __float2half_rn(q2); p1.y = __float2half_rn(q3);
        int base = (tid + i * 128) * 2;
        xqr[base]     = p0;
        xqr[base + 1] = p1;
    }
}

// ============================================================================
// Kernel 2: w (float, values in {-1,0,1}) -> fp16
// ============================================================================
__global__ void __launch_bounds__(512)
wconv_kernel(const float* __restrict__ w, __half* __restrict__ wb)
{
    size_t base = (size_t)blockIdx.x * (512 * 2) + threadIdx.x;  // float4 index
#pragma unroll
    for (int i = 0; i < 2; i++) {
        size_t idx = base + i * 512;
        float4 v = reinterpret_cast<const float4*>(w)[idx];
        __half2 p0, p1;
        p0.x = __float2half_rn(v.x); p0.y = __float2half_rn(v.y);
        p1.x = __float2half_rn(v.z); p1.y = __float2half_rn(v.w);
        reinterpret_cast<__half2*>(wb)[idx * 2]     = p0;
        reinterpret_cast<__half2*>(wb)[idx * 2 + 1] = p1;
    }
}

// ============================================================================
// Kernel 3: fp16 HMMA GEMM, BM=128 x BN=128 x BK=64, 3-stage cp.async pipeline,
// 2 CTAs per SM. 8 warps: 4 (M) x 2 (N); warp tile 32x64.
// FINE-GRAINED DEFERRED PREFETCH: the 8 cp.async chunks for tile kt+2 are
// issued 2 at a time between ksteps, so each LSU clump is ~64 cyc/SMSP and
// always lands while >=2500 cyc of MMA work is queued on the tensor pipe.
// SMEM rows 128 B. Swizzle: o ^ (((o>>7)&7)<<4);
// k-step fragment addr: off[s] = off_base ^ (s<<5).
// ============================================================================
__global__ void __launch_bounds__(THREADS, 2)
bitlinear_gemm(const __half* __restrict__ xq, const __half* __restrict__ wb,
               const float* __restrict__ alpha, float* __restrict__ out)
{
    extern __shared__ int8_t smem[];
    const uint32_t smem_u = smem_to_u32(smem);

    const int tid  = threadIdx.x;
    const int lane = tid & 31;
    const int wid  = tid >> 5;
    const int wm   = wid >> 1;            // 0..3 (M dim)
    const int wn   = wid & 1;             // 0..1 (N dim)

    const int m0 = blockIdx.y * BM;
    const int n0 = blockIdx.x * BN;

    // --- cp.async: A 4 chunks, B 4 chunks per thread per stage ---
    const int ld_row = tid >> 3;           // 0..31
    const int ld_col = tid & 7;
    const int dstA0 = ld_row * TILE_ROW_BYTES +
                      ((ld_col * 16) ^ ((ld_row & 7) << 4));
    const int dstB0 = A_TILE_BYTES + dstA0;
    const int8_t* gA0 = reinterpret_cast<const int8_t*>(xq) +
                        ((size_t)(m0 + ld_row) * K_DIM) * 2 + ld_col * 16;
    const int8_t* gB0 = reinterpret_cast<const int8_t*>(wb) +
                        ((size_t)(n0 + ld_row) * K_DIM) * 2 + ld_col * 16;
    const size_t GSTEP = (size_t)32 * K_DIM * 2;   // 32 rows in gmem bytes

    // --- ldmatrix base offsets (k-step 0); off[s] = base ^ (s<<5) ---
    const int g  = lane >> 3;
    const int lr = lane & 7;
    int offA[2], offB[4];
#pragma unroll
    for (int f = 0; f < 2; f++) {
        int row = wm * 32 + f * 16 + (g & 1) * 8 + lr;
        int kb  = (g >> 1) * 16;
        offA[f] = row * TILE_ROW_BYTES + (kb ^ ((row & 7) << 4));
    }
#pragma unroll
    for (int j2 = 0; j2 < 4; j2++) {
        int row = wn * 64 + j2 * 16 + (g & 1) * 8 + lr;
        int kb  = (g >> 1) * 16;
        offB[j2] = A_TILE_BYTES + row * TILE_ROW_BYTES + (kb ^ ((row & 7) << 4));
    }

    float acc[2][8][4];                   // [m-frag][n8-frag][4] = 64 regs
#pragma unroll
    for (int f = 0; f < 2; f++)
#pragma unroll
        for (int j = 0; j < 8; j++)
#pragma unroll
            for (int c = 0; c < 4; c++) acc[f][j][c] = 0.0f;

    // --- prologue: issue STAGES-1 stages ---
#pragma unroll
    for (int s = 0; s < STAGES - 1; s++) {
        const uint32_t sb = smem_u + s * STAGE_BYTES;
#pragma unroll
        for (int i = 0; i < 4; i++)
            cp_async16(sb + dstA0 + i * 4096, gA0 + i * GSTEP + s * (BK * 2));
#pragma unroll
        for (int i = 0; i < 4; i++)
            cp_async16(sb + dstB0 + i * 4096, gB0 + i * GSTEP + s * (BK * 2));
        cp_commit();
    }

    // --- mainloop (fine-grained deferred prefetch) ---
    int cur = 0;
    int nxt = STAGES - 1;
    for (int kt = 0; kt < NK; kt++) {
        cp_wait<STAGES - 2>();
        __syncthreads();

        const uint32_t st = smem_u + cur * STAGE_BYTES;
        const int jt = kt + STAGES - 1;
        const uint32_t sb = smem_u + nxt * STAGE_BYTES;
        const bool do_pf = (jt < NK);

#pragma unroll
        for (int s = 0; s < 4; s++) {
            const int sx = s << 5;
            uint32_t af[2][4], bf[4][4];
#pragma unroll
            for (int f = 0; f < 2; f++)    ldsm_x4(st + (offA[f] ^ sx), af[f]);
#pragma unroll
            for (int j2 = 0; j2 < 4; j2++) ldsm_x4(st + (offB[j2] ^ sx), bf[j2]);
            // bf[j2] regs: {n0-7 k0-7, n8-15 k0-7, n0-7 k8-15, n8-15 k8-15}
#pragma unroll
            for (int f = 0; f < 2; f++)
#pragma unroll
                for (int j = 0; j < 8; j++)
                    mma_f16(acc[f][j],
                            af[f][0], af[f][1], af[f][2], af[f][3],
                            bf[j >> 1][(j & 1)], bf[j >> 1][(j & 1) + 2]);

            // 2 prefetch chunks after each kstep (A on s=0/1, B on s=2/3
            // issued as: s0 -> A0,A1 ; s1 -> A2,A3 ; s2 -> B0,B1 ;
            // s3 -> B2,B3 + commit)
            if (do_pf) {
                if (s == 0) {
                    cp_async16(sb + dstA0,          gA0 +             jt * (BK * 2));
                    cp_async16(sb + dstA0 + 4096,   gA0 + GSTEP +     jt * (BK * 2));
                } else if (s == 1) {
                    cp_async16(sb + dstA0 + 8192,   gA0 + 2 * GSTEP + jt * (BK * 2));
                    cp_async16(sb + dstA0 + 12288,  gA0 + 3 * GSTEP + jt * (BK * 2));
                } else if (s == 2) {
                    cp_async16(sb + dstB0,          gB0 +             jt * (BK * 2));
                    cp_async16(sb + dstB0 + 4096,   gB0 + GSTEP +     jt * (BK * 2));
                } else {
                    cp_async16(sb + dstB0 + 8192,   gB0 + 2 * GSTEP + jt * (BK * 2));
                    cp_async16(sb + dstB0 + 12288,  gB0 + 3 * GSTEP + jt * (BK * 2));
                }
            }
            if (s == 3) cp_commit();
        }

        cur = (cur == STAGES - 1) ? 0 : cur + 1;
        nxt = (nxt == STAGES - 1) ? 0 : nxt + 1;
    }

    // --- epilogue: dequantize + store ---
#pragma unroll
    for (int f = 0; f < 2; f++) {
        int r0 = m0 + wm * 32 + f * 16 + (lane >> 2);
        float al0 = alpha[r0];
        float al1 = alpha[r0 + 8];
        float* o0 = out + (size_t)r0 * N_DIM + n0 + wn * 64 + (lane & 3) * 2;
        float* o1 = o0 + (size_t)8 * N_DIM;
#pragma unroll
        for (int j = 0; j < 8; j++) {
            float2 v0, v1;
            v0.x = acc[f][j][0] * al0;
            v0.y = acc[f][j][1] * al0;
            v1.x = acc[f][j][2] * al1;
            v1.y = acc[f][j][3] * al1;
            *reinterpret_cast<float2*>(o0 + j * 8) = v0;
            *reinterpret_cast<float2*>(o1 + j * 8) = v1;
        }
    }
}

// ============================================================================
// Host side
// ============================================================================
extern "C" void kernel_launch(void* const* d_in, const int* in_sizes, int n_in,
                              void* d_out, int out_size)
{
    const float* x     = (const float*)d_in[0];
    const float* w     = (const float*)d_in[1];
    const float* scale = (const float*)d_in[2];
    float* out = (float*)d_out;

    void *xq_p = nullptr, *wb_p = nullptr, *al_p = nullptr;
    cudaGetSymbolAddress(&xq_p, g_xq);
    cudaGetSymbolAddress(&wb_p, g_wb);
    cudaGetSymbolAddress(&al_p, g_alpha);

    // Phase 1: quantize activations + convert weights
    quant_kernel<<<M_TOK, 128>>>(x, scale, (__half*)xq_p, (float*)al_p);
    wconv_kernel<<<((size_t)N_DIM * K_DIM) / (512 * 4 * 2), 512>>>(
        w, (__half*)wb_p);

    // Phase 2: GEMM (2 CTAs per SM, fine-grained deferred prefetch)
    cudaFuncSetAttribute(bitlinear_gemm,
                         cudaFuncAttributeMaxDynamicSharedMemorySize, SMEM_TOTAL);
    dim3 grid(N_DIM / BN, M_TOK / BM);   // 32 x 64 = 2048 CTAs
    bitlinear_gemm<<<grid, THREADS, SMEM_TOTAL>>>(
        (const __half*)xq_p, (const __half*)wb_p, (const float*)al_p, out);
}